// round 2
// baseline (speedup 1.0000x reference)
#include <cuda_runtime.h>
#include <math.h>

#define NSPK 512
#define UUT  32
#define DIM  512
#define MROW (NSPK * UUT)   // 16384
#define EPSF 1e-8f

// Scratch (device globals; no dynamic allocation allowed)
__device__ float g_cnT[DIM * NSPK];        // normalized centroids, transposed [d][j]  (1 MB)
__device__ float g_sim[(size_t)MROW * NSPK]; // raw dot products e . c_n               (32 MB)
__device__ float g_rowloss[MROW];          // per-row (lse - diag)                     (64 KB)

// ---------------------------------------------------------------------------
// Kernel 1: centroids + normalize, store transposed.
// Block j handles speaker j. 256 threads, each owns dims {tid, tid+256}.
// c_n[j] = sum_u e[j,u,:] / || sum_u e[j,u,:] ||   (the /32 cancels under norm)
// ---------------------------------------------------------------------------
__global__ __launch_bounds__(256) void centroid_kernel(const float* __restrict__ e) {
    int j = blockIdx.x;
    int tid = threadIdx.x;
    const float* base = e + (size_t)j * UUT * DIM;
    float s0 = 0.f, s1 = 0.f;
#pragma unroll 4
    for (int u = 0; u < UUT; ++u) {
        s0 += base[u * DIM + tid];
        s1 += base[u * DIM + tid + 256];
    }
    __shared__ float red[256];
    red[tid] = s0 * s0 + s1 * s1;
    __syncthreads();
    for (int s = 128; s > 0; s >>= 1) {
        if (tid < s) red[tid] += red[tid + s];
        __syncthreads();
    }
    float inv = 1.0f / fmaxf(sqrtf(red[0]), EPSF);
    g_cnT[(size_t)tid * NSPK + j]         = s0 * inv;
    g_cnT[(size_t)(tid + 256) * NSPK + j] = s1 * inv;
}

// ---------------------------------------------------------------------------
// Kernel 2: SGEMM  g_sim[M][N] = A[M][D] * g_cnT[D][N]
// 128x128 block tile, K-tile 8, 256 threads, 8x8 micro-tile per thread.
// Exact tiling: 16384/128=128 blocks in y, 512/128=4 in x, 512/8=64 K-steps.
// ---------------------------------------------------------------------------
#define BM 128
#define BN 128
#define BK 8

__global__ __launch_bounds__(256) void gemm_kernel(const float* __restrict__ A) {
    __shared__ float As[BK][BM];
    __shared__ float Bs[BK][BN];

    int tid = threadIdx.x;
    int tx = tid & 15;        // 0..15 -> column group
    int ty = tid >> 4;        // 0..15 -> row group
    int rowBase = blockIdx.y * BM;
    int colBase = blockIdx.x * BN;

    float acc[8][8];
#pragma unroll
    for (int i = 0; i < 8; ++i)
#pragma unroll
        for (int j2 = 0; j2 < 8; ++j2) acc[i][j2] = 0.f;

    int aRow = tid >> 1;        // 0..127
    int aCol = (tid & 1) * 4;   // 0 or 4
    int bRow = tid >> 5;        // 0..7
    int bCol = (tid & 31) * 4;  // 0..124

    const float* Aptr = A + (size_t)(rowBase + aRow) * DIM + aCol;
    const float* Bptr = g_cnT + (size_t)bRow * NSPK + colBase + bCol;

    for (int k0 = 0; k0 < DIM; k0 += BK) {
        float4 av = *reinterpret_cast<const float4*>(Aptr + k0);
        float4 bv = *reinterpret_cast<const float4*>(Bptr + (size_t)k0 * NSPK);
        As[aCol + 0][aRow] = av.x;
        As[aCol + 1][aRow] = av.y;
        As[aCol + 2][aRow] = av.z;
        As[aCol + 3][aRow] = av.w;
        *reinterpret_cast<float4*>(&Bs[bRow][bCol]) = bv;
        __syncthreads();

#pragma unroll
        for (int kk = 0; kk < BK; ++kk) {
            float af[8], bf[8];
#pragma unroll
            for (int i = 0; i < 8; ++i) af[i] = As[kk][ty * 8 + i];
#pragma unroll
            for (int j2 = 0; j2 < 8; ++j2) bf[j2] = Bs[kk][tx * 8 + j2];
#pragma unroll
            for (int i = 0; i < 8; ++i)
#pragma unroll
                for (int j2 = 0; j2 < 8; ++j2)
                    acc[i][j2] = fmaf(af[i], bf[j2], acc[i][j2]);
        }
        __syncthreads();
    }

#pragma unroll
    for (int i = 0; i < 8; ++i) {
        int r = rowBase + ty * 8 + i;
        float* out = g_sim + (size_t)r * NSPK + colBase + tx * 8;
#pragma unroll
        for (int j2 = 0; j2 < 8; j2 += 4) {
            float4 v = make_float4(acc[i][j2], acc[i][j2 + 1],
                                   acc[i][j2 + 2], acc[i][j2 + 3]);
            *reinterpret_cast<float4*>(out + j2) = v;
        }
    }
}

// ---------------------------------------------------------------------------
// Kernel 3: per-row logsumexp - diag.  One block per row (16384 blocks).
// Recomputes the query-row norm from e (row-uniform scale; b cancels in lse
// but kept for fidelity).
// ---------------------------------------------------------------------------
__global__ __launch_bounds__(256) void rowreduce_kernel(const float* __restrict__ e,
                                                        const float* __restrict__ wp,
                                                        const float* __restrict__ bp) {
    int r = blockIdx.x;
    int tid = threadIdx.x;
    int j = r >> 5;  // speaker index = diag column
    __shared__ float red[256];

    // ||e_row||
    const float* er = e + (size_t)r * DIM;
    float a0 = er[tid], a1 = er[tid + 256];
    red[tid] = a0 * a0 + a1 * a1;
    __syncthreads();
    for (int s = 128; s > 0; s >>= 1) {
        if (tid < s) red[tid] += red[tid + s];
        __syncthreads();
    }
    float inv = 1.0f / fmaxf(sqrtf(red[0]), EPSF);
    float w = *wp, b = *bp;
    float scale = w * inv;

    const float* sr = g_sim + (size_t)r * NSPK;
    float v0 = sr[tid] * scale + b;
    float v1 = sr[tid + 256] * scale + b;

    // max
    __syncthreads();
    red[tid] = fmaxf(v0, v1);
    __syncthreads();
    for (int s = 128; s > 0; s >>= 1) {
        if (tid < s) red[tid] = fmaxf(red[tid], red[tid + s]);
        __syncthreads();
    }
    float mx = red[0];

    // sum exp
    __syncthreads();
    red[tid] = expf(v0 - mx) + expf(v1 - mx);
    __syncthreads();
    for (int s = 128; s > 0; s >>= 1) {
        if (tid < s) red[tid] += red[tid + s];
        __syncthreads();
    }
    if (tid == 0) {
        float lse = mx + logf(red[0]);
        float vd = sr[j] * scale + b;
        g_rowloss[r] = lse - vd;
    }
}

// ---------------------------------------------------------------------------
// Kernel 4: final mean
// ---------------------------------------------------------------------------
__global__ __launch_bounds__(256) void final_kernel(float* __restrict__ out) {
    int tid = threadIdx.x;
    float s = 0.f;
    for (int i = tid; i < MROW; i += 256) s += g_rowloss[i];
    __shared__ float red[256];
    red[tid] = s;
    __syncthreads();
    for (int st = 128; st > 0; st >>= 1) {
        if (tid < st) red[tid] += red[tid + st];
        __syncthreads();
    }
    if (tid == 0) out[0] = red[0] / (float)MROW;
}

// ---------------------------------------------------------------------------
extern "C" void kernel_launch(void* const* d_in, const int* in_sizes, int n_in,
                              void* d_out, int out_size) {
    const float* e = (const float*)d_in[0];  // (512, 32, 512) fp32
    const float* w = (const float*)d_in[1];  // scalar
    const float* b = (const float*)d_in[2];  // scalar
    float* out = (float*)d_out;

    centroid_kernel<<<NSPK, 256>>>(e);
    gemm_kernel<<<dim3(NSPK / BN, MROW / BM), 256>>>(e);
    rowreduce_kernel<<<MROW, 256>>>(e, w, b);
    final_kernel<<<1, 256>>>(out);
}

// round 6
// speedup vs baseline: 3.3023x; 3.3023x over previous
#include <cuda_runtime.h>
#include <cuda_bf16.h>
#include <math.h>
#include <stdint.h>

#define NSPK 512
#define UUT  32
#define DIM  512
#define MROW 16384          // 512*32
#define KP   1024           // K' = [Bhi ; Blo]
#define EPSF 1e-8f

// ------------------------- device scratch (no allocs) ------------------------
__device__ __nv_bfloat16 g_A[(size_t)MROW * DIM];    // 16 MB, bf16(e)
__device__ __nv_bfloat16 g_B[(size_t)KP * NSPK];     // 1 MB, [k'][n]: k'<512 hi, >=512 lo
__device__ float g_invA[MROW];
__device__ float g_sim[(size_t)MROW * NSPK];         // 32 MB raw dot products

// ------------------------------- PTX helpers ---------------------------------
__device__ __forceinline__ uint32_t smem_u32(const void* p) {
    uint32_t a;
    asm("{ .reg .u64 t; cvta.to.shared.u64 t, %1; cvt.u32.u64 %0, t; }"
        : "=r"(a) : "l"(p));
    return a;
}

#define CP_ASYNC16(dst, src) \
    asm volatile("cp.async.cg.shared.global [%0], [%1], 16;" :: "r"(dst), "l"(src))
#define CP_COMMIT() asm volatile("cp.async.commit_group;" ::: "memory")
#define CP_WAIT1()  asm volatile("cp.async.wait_group 1;" ::: "memory")
#define CP_WAIT0()  asm volatile("cp.async.wait_group 0;" ::: "memory")

#define LDSM_X4(r, addr) \
    asm volatile("ldmatrix.sync.aligned.m8n8.x4.shared.b16 {%0,%1,%2,%3}, [%4];" \
        : "=r"((r)[0]), "=r"((r)[1]), "=r"((r)[2]), "=r"((r)[3]) : "r"(addr))
#define LDSM_X4T(r, addr) \
    asm volatile("ldmatrix.sync.aligned.m8n8.x4.trans.shared.b16 {%0,%1,%2,%3}, [%4];" \
        : "=r"((r)[0]), "=r"((r)[1]), "=r"((r)[2]), "=r"((r)[3]) : "r"(addr))

#define MMA16816(c, a, b0, b1) \
    asm volatile("mma.sync.aligned.m16n8k16.row.col.f32.bf16.bf16.f32 " \
        "{%0,%1,%2,%3}, {%4,%5,%6,%7}, {%8,%9}, {%0,%1,%2,%3};" \
        : "+f"((c)[0]), "+f"((c)[1]), "+f"((c)[2]), "+f"((c)[3]) \
        : "r"((a)[0]), "r"((a)[1]), "r"((a)[2]), "r"((a)[3]), "r"(b0), "r"(b1))

// Swizzled smem offsets (conflict-free for both cp.async stores & ldmatrix)
// A tile: 128 rows x 64B (32 bf16). Pack 2 rows/128B line, XOR 3-bit swizzle.
__device__ __forceinline__ uint32_t aoff(int row, int g) {
    int line = row >> 1;
    int gi = ((row & 1) << 2) | g;           // 0..7 granules per 128B line
    return (uint32_t)(line * 128 + ((gi ^ (line & 7)) << 4));
}
// B tile: 32 rows (k) x 256B (128 bf16), 16 granules/row, XOR with k&7.
__device__ __forceinline__ uint32_t boff(int k, int g) {
    return (uint32_t)(k * 256 + ((g ^ (k & 7)) << 4));
}

// -----------------------------------------------------------------------------
// Kernel 1: e -> bf16 + inverse row norm. One warp per row. Also zeroes d_out.
// -----------------------------------------------------------------------------
__global__ __launch_bounds__(256) void convA_kernel(const float* __restrict__ e,
                                                    float* __restrict__ out) {
    if (blockIdx.x == 0 && threadIdx.x == 0) out[0] = 0.f;
    int w = threadIdx.x >> 5, lane = threadIdx.x & 31;
    int r = blockIdx.x * 8 + w;
    const float4* src = (const float4*)(e + (size_t)r * DIM);
    __nv_bfloat162* dst = (__nv_bfloat162*)(g_A + (size_t)r * DIM);
    float ss = 0.f;
#pragma unroll
    for (int i = 0; i < 4; ++i) {
        float4 v = src[i * 32 + lane];
        ss += v.x * v.x + v.y * v.y + v.z * v.z + v.w * v.w;
        __nv_bfloat162 p0, p1;
        p0.x = __float2bfloat16(v.x); p0.y = __float2bfloat16(v.y);
        p1.x = __float2bfloat16(v.z); p1.y = __float2bfloat16(v.w);
        dst[(i * 32 + lane) * 2]     = p0;
        dst[(i * 32 + lane) * 2 + 1] = p1;
    }
#pragma unroll
    for (int s = 16; s > 0; s >>= 1) ss += __shfl_xor_sync(0xffffffffu, ss, s);
    if (lane == 0) g_invA[r] = 1.0f / fmaxf(sqrtf(ss), EPSF);
}

// -----------------------------------------------------------------------------
// Kernel 2: centroid sum + normalize -> bf16 hi/lo into g_B [k'][n]
// -----------------------------------------------------------------------------
__global__ __launch_bounds__(256) void centroid_kernel(const float* __restrict__ e) {
    int j = blockIdx.x, tid = threadIdx.x;
    const float* base = e + (size_t)j * UUT * DIM;
    float s0 = 0.f, s1 = 0.f;
#pragma unroll 4
    for (int u = 0; u < UUT; ++u) {
        s0 += base[u * DIM + tid];
        s1 += base[u * DIM + tid + 256];
    }
    __shared__ float red[256];
    red[tid] = s0 * s0 + s1 * s1;
    __syncthreads();
    for (int s = 128; s > 0; s >>= 1) {
        if (tid < s) red[tid] += red[tid + s];
        __syncthreads();
    }
    // c_n = sum / max(||sum||, 32*eps)   (mean /32 cancels under the norm)
    float inv = 1.0f / fmaxf(sqrtf(red[0]), 32.f * EPSF);
    float c0 = s0 * inv, c1 = s1 * inv;
    __nv_bfloat16 h0 = __float2bfloat16(c0);
    __nv_bfloat16 h1 = __float2bfloat16(c1);
    g_B[(size_t)tid * NSPK + j]               = h0;
    g_B[(size_t)(tid + 256) * NSPK + j]       = h1;
    g_B[(size_t)(512 + tid) * NSPK + j]       = __float2bfloat16(c0 - __bfloat162float(h0));
    g_B[(size_t)(512 + tid + 256) * NSPK + j] = __float2bfloat16(c1 - __bfloat162float(h1));
}

// -----------------------------------------------------------------------------
// Kernel 3: bf16 mma.sync GEMM  g_sim[16384][512] = A[16384][512] * B'[1024][512]
// (A reused for both K halves).  BM=128 BN=128 BK=32, 256 thr, cp.async 2-stage.
// -----------------------------------------------------------------------------
#define NSTAGE_K 32   // KP / 32

__global__ __launch_bounds__(256) void gemm_kernel() {
    __shared__ __align__(1024) char smem[32768];  // A: [2][8K] @0, B: [2][8K] @16K

    int tid = threadIdx.x;
    int lane = tid & 31, wid = tid >> 5;
    int warp_m = wid & 1, warp_n = wid >> 1;       // 2 x 4 warp grid
    int mBase = blockIdx.y * 128, nBase = blockIdx.x * 128;

    uint32_t sbase = smem_u32(smem);

    // cp.async store slots (2 passes each for A and B)
    int arow0 = tid >> 2, ag = tid & 3;
    uint32_t aoffs0 = aoff(arow0, ag), aoffs1 = aoff(arow0 + 64, ag);
    const __nv_bfloat16* aptr0 = g_A + (size_t)(mBase + arow0) * DIM + ag * 8;
    const __nv_bfloat16* aptr1 = aptr0 + (size_t)64 * DIM;

    int brow0 = tid >> 4, bg = tid & 15;
    uint32_t boffs0 = boff(brow0, bg), boffs1 = boff(brow0 + 16, bg);
    const __nv_bfloat16* bptr0 = g_B + (size_t)brow0 * NSPK + nBase + bg * 8;
    const __nv_bfloat16* bptr1 = bptr0 + (size_t)16 * NSPK;

    float c[4][4][4];
#pragma unroll
    for (int i = 0; i < 4; ++i)
#pragma unroll
        for (int j = 0; j < 4; ++j)
#pragma unroll
            for (int q = 0; q < 4; ++q) c[i][j][q] = 0.f;

#define LOAD_STAGE(s, kt) do {                                                  \
        int k0 = (kt) * 32;                                                     \
        int ka = k0 & (DIM - 1);                                                \
        uint32_t sA_ = sbase + (s) * 8192;                                      \
        uint32_t sB_ = sbase + 16384 + (s) * 8192;                              \
        CP_ASYNC16(sA_ + aoffs0, aptr0 + ka);                                   \
        CP_ASYNC16(sA_ + aoffs1, aptr1 + ka);                                   \
        CP_ASYNC16(sB_ + boffs0, bptr0 + (size_t)k0 * NSPK);                    \
        CP_ASYNC16(sB_ + boffs1, bptr1 + (size_t)k0 * NSPK);                    \
        CP_COMMIT();                                                            \
    } while (0)

    LOAD_STAGE(0, 0);
    LOAD_STAGE(1, 1);

    int lrow = lane & 15, lsel = lane >> 4;

    for (int kt = 0; kt < NSTAGE_K; ++kt) {
        if (kt < NSTAGE_K - 1) CP_WAIT1(); else CP_WAIT0();
        __syncthreads();

        int s = kt & 1;
        uint32_t sA = sbase + s * 8192;
        uint32_t sB = sbase + 16384 + s * 8192;

#pragma unroll
        for (int kh = 0; kh < 2; ++kh) {
            uint32_t a[4][4], b[2][4];
#pragma unroll
            for (int mt = 0; mt < 4; ++mt) {
                int row = warp_m * 64 + mt * 16 + lrow;
                int g = kh * 2 + lsel;
                LDSM_X4(a[mt], sA + aoff(row, g));
            }
#pragma unroll
            for (int nt = 0; nt < 2; ++nt) {
                int k = kh * 16 + lrow;
                int g = warp_n * 4 + nt * 2 + lsel;
                LDSM_X4T(b[nt], sB + boff(k, g));
            }
#pragma unroll
            for (int mt = 0; mt < 4; ++mt)
#pragma unroll
                for (int n8 = 0; n8 < 4; ++n8) {
                    uint32_t b0 = b[n8 >> 1][(n8 & 1) * 2];
                    uint32_t b1 = b[n8 >> 1][(n8 & 1) * 2 + 1];
                    MMA16816(c[mt][n8], a[mt], b0, b1);
                }
        }
        __syncthreads();
        if (kt + 2 < NSTAGE_K) LOAD_STAGE(kt & 1, kt + 2);
    }

    // Store accumulators (raw dot products)
#pragma unroll
    for (int mt = 0; mt < 4; ++mt) {
        int row = mBase + warp_m * 64 + mt * 16 + (lane >> 2);
#pragma unroll
        for (int n8 = 0; n8 < 4; ++n8) {
            int col = nBase + warp_n * 32 + n8 * 8 + (lane & 3) * 2;
            float2 v0 = make_float2(c[mt][n8][0], c[mt][n8][1]);
            float2 v1 = make_float2(c[mt][n8][2], c[mt][n8][3]);
            *(float2*)&g_sim[(size_t)row * NSPK + col] = v0;
            *(float2*)&g_sim[(size_t)(row + 8) * NSPK + col] = v1;
        }
    }
#undef LOAD_STAGE
}

// -----------------------------------------------------------------------------
// Kernel 4: fused row logsumexp - diag + mean accumulation.
// One warp per row; sim in [-1,1] => v in [-15,5], no max pass needed.
// -----------------------------------------------------------------------------
__global__ __launch_bounds__(256) void rowreduce_kernel(const float* __restrict__ wp,
                                                        const float* __restrict__ bp,
                                                        float* __restrict__ out) {
    int wid = threadIdx.x >> 5, lane = threadIdx.x & 31;
    int r = blockIdx.x * 8 + wid;
    float wv = *wp, bv = *bp;
    float scale = wv * g_invA[r];
    const float4* sr = (const float4*)(g_sim + (size_t)r * NSPK);
    float se = 0.f;
#pragma unroll
    for (int i = 0; i < 4; ++i) {
        float4 v = sr[i * 32 + lane];
        se += __expf(fmaf(v.x, scale, bv));
        se += __expf(fmaf(v.y, scale, bv));
        se += __expf(fmaf(v.z, scale, bv));
        se += __expf(fmaf(v.w, scale, bv));
    }
#pragma unroll
    for (int s = 16; s > 0; s >>= 1) se += __shfl_xor_sync(0xffffffffu, se, s);

    __shared__ float part[8];
    if (lane == 0) {
        int j = r >> 5;  // diag column (speaker index)
        float vd = fmaf(g_sim[(size_t)r * NSPK + j], scale, bv);
        part[wid] = __logf(se) - vd;
    }
    __syncthreads();
    if (threadIdx.x == 0) {
        float s = 0.f;
#pragma unroll
        for (int i = 0; i < 8; ++i) s += part[i];
        atomicAdd(out, s * (1.0f / (float)MROW));
    }
}

// -----------------------------------------------------------------------------
extern "C" void kernel_launch(void* const* d_in, const int* in_sizes, int n_in,
                              void* d_out, int out_size) {
    const float* e = (const float*)d_in[0];  // (512, 32, 512) fp32
    const float* w = (const float*)d_in[1];
    const float* b = (const float*)d_in[2];
    float* out = (float*)d_out;

    convA_kernel<<<MROW / 8, 256>>>(e, out);
    centroid_kernel<<<NSPK, 256>>>(e);
    gemm_kernel<<<dim3(NSPK / 128, MROW / 128), 256>>>();
    rowreduce_kernel<<<MROW / 8, 256>>>(w, b, out);
}

// round 7
// speedup vs baseline: 5.4386x; 1.6469x over previous
#include <cuda_runtime.h>
#include <cuda_bf16.h>
#include <math.h>
#include <stdint.h>

#define NSPK 512
#define UUT  32
#define DIM  512
#define MROW 16384          // 512*32
#define EPSF 1e-8f

// ------------------------- device scratch (no allocs) ------------------------
__device__ __nv_bfloat16 g_A[(size_t)MROW * DIM];   // 16 MB bf16(e)
__device__ __nv_bfloat16 g_B[(size_t)DIM * NSPK];   // 512x512 normalized centroids [k][n]
__device__ float g_invA[MROW];
__device__ float g_se[MROW];                        // sum of exp per row
__device__ float g_vd[MROW];                        // diag value per row

// ------------------------------- PTX helpers ---------------------------------
__device__ __forceinline__ uint32_t smem_u32(const void* p) {
    uint32_t a;
    asm("{ .reg .u64 t; cvta.to.shared.u64 t, %1; cvt.u32.u64 %0, t; }"
        : "=r"(a) : "l"(p));
    return a;
}

#define CP_ASYNC16(dst, src) \
    asm volatile("cp.async.cg.shared.global [%0], [%1], 16;" :: "r"(dst), "l"(src))
#define CP_COMMIT() asm volatile("cp.async.commit_group;" ::: "memory")
#define CP_WAIT1()  asm volatile("cp.async.wait_group 1;" ::: "memory")
#define CP_WAIT0()  asm volatile("cp.async.wait_group 0;" ::: "memory")

#define LDSM_X4(r, addr) \
    asm volatile("ldmatrix.sync.aligned.m8n8.x4.shared.b16 {%0,%1,%2,%3}, [%4];" \
        : "=r"((r)[0]), "=r"((r)[1]), "=r"((r)[2]), "=r"((r)[3]) : "r"(addr))
#define LDSM_X4T(r, addr) \
    asm volatile("ldmatrix.sync.aligned.m8n8.x4.trans.shared.b16 {%0,%1,%2,%3}, [%4];" \
        : "=r"((r)[0]), "=r"((r)[1]), "=r"((r)[2]), "=r"((r)[3]) : "r"(addr))

#define MMA16816(c, a, b0, b1) \
    asm volatile("mma.sync.aligned.m16n8k16.row.col.f32.bf16.bf16.f32 " \
        "{%0,%1,%2,%3}, {%4,%5,%6,%7}, {%8,%9}, {%0,%1,%2,%3};" \
        : "+f"((c)[0]), "+f"((c)[1]), "+f"((c)[2]), "+f"((c)[3]) \
        : "r"((a)[0]), "r"((a)[1]), "r"((a)[2]), "r"((a)[3]), "r"(b0), "r"(b1))

// Swizzled smem offsets (identical scheme validated in the passing R5 kernel)
__device__ __forceinline__ uint32_t aoff(int row, int g) {
    int line = row >> 1;
    int gi = ((row & 1) << 2) | g;
    return (uint32_t)(line * 128 + ((gi ^ (line & 7)) << 4));
}
__device__ __forceinline__ uint32_t boff(int k, int g) {
    return (uint32_t)(k * 256 + ((g ^ (k & 7)) << 4));
}

// -----------------------------------------------------------------------------
// Kernel 1 (fused prep): per speaker block j reads its 32x512 slice ONCE.
//  - bf16-convert all 32 rows into g_A + per-row inv norms
//  - centroid sum -> normalize -> bf16 into g_B [k][n]
//  - zero g_se rows and d_out
// -----------------------------------------------------------------------------
__global__ __launch_bounds__(256) void prep_kernel(const float* __restrict__ e,
                                                   float* __restrict__ out) {
    int j = blockIdx.x, tid = threadIdx.x;
    int w = tid >> 5, lane = tid & 31;
    if (j == 0 && tid == 0) out[0] = 0.f;
    if (tid < 32) g_se[j * 32 + tid] = 0.f;

    __shared__ float cpart[8][512];   // per-warp centroid partials (16 KB)

    float acc[16];
#pragma unroll
    for (int i = 0; i < 16; ++i) acc[i] = 0.f;

#pragma unroll
    for (int uu = 0; uu < 4; ++uu) {
        int u = w * 4 + uu;
        int r = j * UUT + u;
        const float4* src = (const float4*)(e + (size_t)r * DIM);
        __nv_bfloat162* dst = (__nv_bfloat162*)(g_A + (size_t)r * DIM);
        float ss = 0.f;
#pragma unroll
        for (int i = 0; i < 4; ++i) {
            float4 v = src[i * 32 + lane];
            ss += v.x * v.x + v.y * v.y + v.z * v.z + v.w * v.w;
            acc[i * 4 + 0] += v.x; acc[i * 4 + 1] += v.y;
            acc[i * 4 + 2] += v.z; acc[i * 4 + 3] += v.w;
            __nv_bfloat162 p0, p1;
            p0.x = __float2bfloat16(v.x); p0.y = __float2bfloat16(v.y);
            p1.x = __float2bfloat16(v.z); p1.y = __float2bfloat16(v.w);
            dst[(i * 32 + lane) * 2]     = p0;
            dst[(i * 32 + lane) * 2 + 1] = p1;
        }
#pragma unroll
        for (int s = 16; s > 0; s >>= 1) ss += __shfl_xor_sync(0xffffffffu, ss, s);
        if (lane == 0) g_invA[r] = 1.0f / fmaxf(sqrtf(ss), EPSF);
    }

#pragma unroll
    for (int i = 0; i < 4; ++i) {
        int d = (i * 32 + lane) * 4;
        cpart[w][d + 0] = acc[i * 4 + 0];
        cpart[w][d + 1] = acc[i * 4 + 1];
        cpart[w][d + 2] = acc[i * 4 + 2];
        cpart[w][d + 3] = acc[i * 4 + 3];
    }
    __syncthreads();

    float c0 = 0.f, c1 = 0.f;
#pragma unroll
    for (int p = 0; p < 8; ++p) {
        c0 += cpart[p][tid];
        c1 += cpart[p][tid + 256];
    }
    __syncthreads();
    // reuse cpart[0] for norm reduction
    cpart[0][tid] = c0 * c0 + c1 * c1;
    __syncthreads();
    for (int s = 128; s > 0; s >>= 1) {
        if (tid < s) cpart[0][tid] += cpart[0][tid + s];
        __syncthreads();
    }
    float inv = 1.0f / fmaxf(sqrtf(cpart[0][0]), 32.f * EPSF);
    g_B[(size_t)tid * NSPK + j]         = __float2bfloat16(c0 * inv);
    g_B[(size_t)(tid + 256) * NSPK + j] = __float2bfloat16(c1 * inv);
}

// -----------------------------------------------------------------------------
// Kernel 2: bf16 mma.sync GEMM (K=512) with FUSED softmax-partial epilogue.
// BM=128 BN=128 BK=32, 256 thr, cp.async double buffer.
// Epilogue: partial sum-exp per row -> atomicAdd(g_se); diag tile writes g_vd.
// -----------------------------------------------------------------------------
#define NSTAGE_K 16   // DIM / 32

__global__ __launch_bounds__(256) void gemm_fused_kernel(const float* __restrict__ wp,
                                                         const float* __restrict__ bp) {
    __shared__ __align__(1024) char smem[32768];
    __shared__ float se_sm[128];

    int tid = threadIdx.x;
    int lane = tid & 31, wid = tid >> 5;
    int warp_m = wid & 1, warp_n = wid >> 1;
    int mBase = blockIdx.y * 128, nBase = blockIdx.x * 128;

    uint32_t sbase = smem_u32(smem);

    int arow0 = tid >> 2, ag = tid & 3;
    uint32_t aoffs0 = aoff(arow0, ag), aoffs1 = aoff(arow0 + 64, ag);
    const __nv_bfloat16* aptr0 = g_A + (size_t)(mBase + arow0) * DIM + ag * 8;
    const __nv_bfloat16* aptr1 = aptr0 + (size_t)64 * DIM;

    int brow0 = tid >> 4, bg = tid & 15;
    uint32_t boffs0 = boff(brow0, bg), boffs1 = boff(brow0 + 16, bg);
    const __nv_bfloat16* bptr0 = g_B + (size_t)brow0 * NSPK + nBase + bg * 8;
    const __nv_bfloat16* bptr1 = bptr0 + (size_t)16 * NSPK;

    if (tid < 128) se_sm[tid] = 0.f;

    float c[4][4][4];
#pragma unroll
    for (int i = 0; i < 4; ++i)
#pragma unroll
        for (int j = 0; j < 4; ++j)
#pragma unroll
            for (int q = 0; q < 4; ++q) c[i][j][q] = 0.f;

#define LOAD_STAGE(s, kt) do {                                                  \
        int k0 = (kt) * 32;                                                     \
        uint32_t sA_ = sbase + (s) * 8192;                                      \
        uint32_t sB_ = sbase + 16384 + (s) * 8192;                              \
        CP_ASYNC16(sA_ + aoffs0, aptr0 + k0);                                   \
        CP_ASYNC16(sA_ + aoffs1, aptr1 + k0);                                   \
        CP_ASYNC16(sB_ + boffs0, bptr0 + (size_t)k0 * NSPK);                    \
        CP_ASYNC16(sB_ + boffs1, bptr1 + (size_t)k0 * NSPK);                    \
        CP_COMMIT();                                                            \
    } while (0)

    LOAD_STAGE(0, 0);
    LOAD_STAGE(1, 1);

    int lrow = lane & 15, lsel = lane >> 4;

    for (int kt = 0; kt < NSTAGE_K; ++kt) {
        if (kt < NSTAGE_K - 1) CP_WAIT1(); else CP_WAIT0();
        __syncthreads();

        int s = kt & 1;
        uint32_t sA = sbase + s * 8192;
        uint32_t sB = sbase + 16384 + s * 8192;

#pragma unroll
        for (int kh = 0; kh < 2; ++kh) {
            uint32_t a[4][4], b[2][4];
#pragma unroll
            for (int mt = 0; mt < 4; ++mt) {
                int row = warp_m * 64 + mt * 16 + lrow;
                LDSM_X4(a[mt], sA + aoff(row, kh * 2 + lsel));
            }
#pragma unroll
            for (int nt = 0; nt < 2; ++nt) {
                int k = kh * 16 + lrow;
                LDSM_X4T(b[nt], sB + boff(k, warp_n * 4 + nt * 2 + lsel));
            }
#pragma unroll
            for (int mt = 0; mt < 4; ++mt)
#pragma unroll
                for (int n8 = 0; n8 < 4; ++n8) {
                    uint32_t b0 = b[n8 >> 1][(n8 & 1) * 2];
                    uint32_t b1 = b[n8 >> 1][(n8 & 1) * 2 + 1];
                    MMA16816(c[mt][n8], a[mt], b0, b1);
                }
        }
        __syncthreads();
        if (kt + 2 < NSTAGE_K) LOAD_STAGE(kt & 1, kt + 2);
    }
#undef LOAD_STAGE

    // ---------------- fused epilogue: partial sum-exp + diag -----------------
    float wv = *wp, bv = *bp;
#pragma unroll
    for (int mt = 0; mt < 4; ++mt) {
#pragma unroll
        for (int sr = 0; sr < 2; ++sr) {
            int row_l = warp_m * 64 + mt * 16 + (lane >> 2) + sr * 8;
            int row_g = mBase + row_l;
            float sc = wv * g_invA[row_g];
            int jdiag = row_g >> 5;
            float part = 0.f;
#pragma unroll
            for (int n8 = 0; n8 < 4; ++n8) {
#pragma unroll
                for (int cc = 0; cc < 2; ++cc) {
                    int col_g = nBase + warp_n * 32 + n8 * 8 + (lane & 3) * 2 + cc;
                    float v = fmaf(c[mt][n8][sr * 2 + cc], sc, bv);
                    part += __expf(v);
                    if (col_g == jdiag) g_vd[row_g] = v;
                }
            }
            part += __shfl_xor_sync(0xffffffffu, part, 1);
            part += __shfl_xor_sync(0xffffffffu, part, 2);
            if ((lane & 3) == 0) atomicAdd(&se_sm[row_l], part);
        }
    }
    __syncthreads();
    if (tid < 128) atomicAdd(&g_se[mBase + tid], se_sm[tid]);
}

// -----------------------------------------------------------------------------
// Kernel 3: loss = mean(log(se) - vd)
// -----------------------------------------------------------------------------
__global__ __launch_bounds__(256) void final_kernel(float* __restrict__ out) {
    int idx = blockIdx.x * 256 + threadIdx.x;
    float v = __logf(g_se[idx]) - g_vd[idx];
#pragma unroll
    for (int s = 16; s > 0; s >>= 1) v += __shfl_xor_sync(0xffffffffu, v, s);
    __shared__ float part[8];
    int wid = threadIdx.x >> 5, lane = threadIdx.x & 31;
    if (lane == 0) part[wid] = v;
    __syncthreads();
    if (threadIdx.x == 0) {
        float s = 0.f;
#pragma unroll
        for (int i = 0; i < 8; ++i) s += part[i];
        atomicAdd(out, s * (1.0f / (float)MROW));
    }
}

// -----------------------------------------------------------------------------
extern "C" void kernel_launch(void* const* d_in, const int* in_sizes, int n_in,
                              void* d_out, int out_size) {
    const float* e = (const float*)d_in[0];  // (512, 32, 512) fp32
    const float* w = (const float*)d_in[1];
    const float* b = (const float*)d_in[2];
    float* out = (float*)d_out;

    prep_kernel<<<NSPK, 256>>>(e, out);
    gemm_fused_kernel<<<dim3(NSPK / 128, MROW / 128), 256>>>(w, b);
    final_kernel<<<MROW / 256, 256>>>(out);
}